// round 10
// baseline (speedup 1.0000x reference)
#include <cuda_runtime.h>
#include <cstdint>

#define NPTS   60000
#define KOFF   27
#define CIN    2
#define COUT   64
#define BB     2
#define DD     12
#define HH     200
#define WW     200
#define CELLS  960000        // 2*12*200*200
#define EPS_LN 1e-5f

#define ROWS_TOTAL (BB * DD * HH)        // 4800 blocks
#define WARPS_PER_BLOCK 8
#define CELLS_PER_WARP  (WW / WARPS_PER_BLOCK)   // 25
#define CHUNK 5                                   // cells processed per phase

#define GROW 202                                  // padded row: [-1 | 200 | -1]
#define EMPTY16 0xFFFFu

// Dense cell -> point-id lookup grid (3.84 MB, L2-resident). -1 = empty.
__device__ int g_pointgrid[CELLS];
// Channel-mean weight vectors: wbar[j] = (1/64) sum_q w_jq  (2-vec).
__device__ float2 g_wbar[KOFF];

// Packed dual-FMA: (d.x, d.y) = a*b + c elementwise, one FFMA2 instruction.
__device__ __forceinline__ float2 ffma2(float2 a, float2 b, float2 c) {
    float2 d;
    asm("fma.rn.f32x2 %0, %1, %2, %3;"
        : "=l"(reinterpret_cast<unsigned long long&>(d))
        : "l"(reinterpret_cast<const unsigned long long&>(a)),
          "l"(reinterpret_cast<const unsigned long long&>(b)),
          "l"(reinterpret_cast<const unsigned long long&>(c)));
    return d;
}

// --------------------------------------------------------------------------
// Kernel 1: init point grid to -1.
// --------------------------------------------------------------------------
__global__ void init_grid_kernel() {
    int i = blockIdx.x * blockDim.x + threadIdx.x;
    if (i < CELLS / 4)
        reinterpret_cast<int4*>(g_pointgrid)[i] = make_int4(-1, -1, -1, -1);
}

// --------------------------------------------------------------------------
// Kernel 2: fill point grid. scat[13*NPTS + n] is point n's own cell index.
// --------------------------------------------------------------------------
__global__ void fill_grid_kernel(const int* __restrict__ scat) {
    int n = blockIdx.x * blockDim.x + threadIdx.x;
    if (n < NPTS)
        g_pointgrid[scat[13 * NPTS + n]] = n;
}

// --------------------------------------------------------------------------
// Kernel 2b: precompute wbar (27 threads, trivial).
// --------------------------------------------------------------------------
__global__ void wbar_kernel(const float* __restrict__ weight) {  // [27,2,64]
    int t = threadIdx.x;
    if (t < KOFF) {
        float s0 = 0.f, s1 = 0.f;
        #pragma unroll 8
        for (int q = 0; q < COUT; q++) {
            s0 += weight[(t * 2 + 0) * COUT + q];
            s1 += weight[(t * 2 + 1) * COUT + q];
        }
        g_wbar[t] = make_float2(s0 * (1.f / COUT), s1 * (1.f / COUT));
    }
}

// --------------------------------------------------------------------------
// Kernel 3: fused gather-conv + LayerNorm + ReLU.
// One block per (b, z, y) row; 9 neighbor grid rows staged as uint16 in smem
// with halo. Warp handles 25 cells in chunks of 5. Lane i owns channels
// {2i, 2i+1}. Hit features bounced through smem as (fx,fx,fy,fy) so the
// channel accumulate is 2 packed FFMA2. Empty chunks short-circuit.
// --------------------------------------------------------------------------
__global__ __launch_bounds__(256, 6) void fused_kernel(
        const float2* __restrict__ feat,     // [NPTS] as float2
        const float2* __restrict__ weight2,  // float2 view of [27,2,64]
        const float*  __restrict__ gamma,
        const float*  __restrict__ beta,
        float* __restrict__ out) {           // [CELLS, 64]
    __shared__ float4 swpx[KOFF][33];                          // 14256 B
    __shared__ unsigned short sgrid[9 * GROW];                 //  3636 B
    __shared__ float4 sfeat4[WARPS_PER_BLOCK][CHUNK][28];      // 17920 B

    // decode row
    const int row = blockIdx.x;          // (b*DD + z)*HH + y
    const int y   = row % HH;
    const int bz  = row / HH;            // b*DD + z
    const int z   = bz % DD;
    const int rowbase = row * WW;        // linear cell index of x=0

    // ---- stage packed weights: swpx[j][lane] = (w0.x, w0.y, w1.x, w1.y) ----
    for (int i = threadIdx.x; i < KOFF * 32; i += blockDim.x) {
        const int j = i >> 5, ln = i & 31;
        const float2 w0 = weight2[(j * 2 + 0) * (COUT / 2) + ln];
        const float2 w1 = weight2[(j * 2 + 1) * (COUT / 2) + ln];
        swpx[j][ln] = make_float4(w0.x, w0.y, w1.x, w1.y);
    }
    if (threadIdx.x < KOFF) {
        const float2 wb = g_wbar[threadIdx.x];
        swpx[threadIdx.x][32] = make_float4(wb.x, wb.y, 0.f, 0.f);
    }

    // ---- stage 9 neighbor grid rows with halo (uint16, 0xFFFF = empty) ----
    for (int i = threadIdx.x; i < 9 * GROW; i += blockDim.x) {
        const int r  = i / GROW;         // 0..8 -> (dz+1)*3 + (dy+1)
        const int c  = i - r * GROW;     // 0..201 -> x = c-1
        const int dz = r / 3 - 1;
        const int dy = r % 3 - 1;
        const int nz = z + dz, ny = y + dy, nx = c - 1;
        int v = -1;
        if ((unsigned)nz < DD && (unsigned)ny < HH && (unsigned)nx < WW)
            v = g_pointgrid[rowbase + (dz * HH + dy) * WW + nx];
        sgrid[i] = (v < 0) ? (unsigned short)EMPTY16 : (unsigned short)v;
    }
    __syncthreads();

    const int lane = threadIdx.x & 31;
    const int wib  = threadIdx.x >> 5;

    const float2 gg = reinterpret_cast<const float2*>(gamma)[lane];
    const float2 bb = reinterpret_cast<const float2*>(beta)[lane];

    // lane -> (k, smem probe base)
    const int dxl   = lane % 3;                         // dx+1 for lanes<27
    const int srow  = (lane < KOFF) ? (lane / 3) : 0;   // (dz+1)*3+(dy+1)
    const int pbase = srow * GROW + dxl;                // + x gives probe index
    const bool probing = (lane < KOFF);

    const int x0 = wib * CELLS_PER_WARP;

    for (int c0 = 0; c0 < CELLS_PER_WARP; c0 += CHUNK) {
        // ---- phase 1: probes (LDS.U16) ----
        unsigned pt[CHUNK];
        #pragma unroll
        for (int ci = 0; ci < CHUNK; ci++) {
            const int x = x0 + c0 + ci;
            pt[ci] = probing ? (unsigned)sgrid[pbase + x] : EMPTY16;
        }

        // ---- phase 2: ballots; empty-chunk fast path; feature gather ----
        unsigned act[CHUNK];
        #pragma unroll
        for (int ci = 0; ci < CHUNK; ci++)
            act[ci] = __ballot_sync(0xffffffffu, pt[ci] != EMPTY16);

        const unsigned any = act[0] | act[1] | act[2] | act[3] | act[4];
        if (any == 0u) {                 // whole chunk inactive: clear poison
            #pragma unroll
            for (int ci = 0; ci < CHUNK; ci++) {
                const int cell = rowbase + x0 + c0 + ci;
                float2* po = reinterpret_cast<float2*>(out + (size_t)cell * COUT) + lane;
                __stcs(po, make_float2(0.f, 0.f));
            }
            continue;
        }

        #pragma unroll
        for (int ci = 0; ci < CHUNK; ci++)
            if (pt[ci] != EMPTY16) {
                const float2 f = __ldg(&feat[pt[ci]]);
                sfeat4[wib][ci][lane] = make_float4(f.x, f.x, f.y, f.y);
            }
        __syncwarp();

        // ---- phase 3: packed channel accumulate + analytic mean ----
        float2 A01[CHUNK];
        float MEAN[CHUNK], SQ[CHUNK];
        #pragma unroll
        for (int ci = 0; ci < CHUNK; ci++) {
            float2 a01 = make_float2(0.f, 0.f);
            float mean = 0.f;
            unsigned hits = act[ci];
            while (hits) {
                const int j = __ffs(hits) - 1;
                hits &= hits - 1;
                const float4 fq = sfeat4[wib][ci][j];     // (fx,fx,fy,fy)
                const float4* base = &swpx[j][0];
                const float4 wp = base[lane];
                const float4 wb = base[32];               // imm-offset broadcast
                a01 = ffma2(make_float2(fq.x, fq.y), make_float2(wp.x, wp.y), a01);
                a01 = ffma2(make_float2(fq.z, fq.w), make_float2(wp.z, wp.w), a01);
                mean = fmaf(fq.x, wb.x, fmaf(fq.z, wb.y, mean));
            }
            A01[ci] = a01;
            MEAN[ci] = mean;
            SQ[ci] = a01.x * a01.x + a01.y * a01.y;
        }

        // ---- phase 4: one interleaved butterfly for sum(a^2) ----
        #pragma unroll
        for (int o = 16; o > 0; o >>= 1) {
            #pragma unroll
            for (int ci = 0; ci < CHUNK; ci++)
                SQ[ci] += __shfl_xor_sync(0xffffffffu, SQ[ci], o);
        }

        // ---- phase 5: normalize + relu + streaming store ----
        #pragma unroll
        for (int ci = 0; ci < CHUNK; ci++) {
            const float var = fmaf(-MEAN[ci], MEAN[ci], SQ[ci] * (1.f / COUT));
            const float inv = rsqrtf(var + EPS_LN);
            const float d0 = A01[ci].x - MEAN[ci];
            const float d1 = A01[ci].y - MEAN[ci];
            float r0 = fmaxf(fmaf(d0 * inv, gg.x, bb.x), 0.f);
            float r1 = fmaxf(fmaf(d1 * inv, gg.y, bb.y), 0.f);
            if (act[ci] == 0u) { r0 = 0.f; r1 = 0.f; }
            const int cell = rowbase + x0 + c0 + ci;
            float2* po = reinterpret_cast<float2*>(out + (size_t)cell * COUT) + lane;
            __stcs(po, make_float2(r0, r1));   // streaming: don't thrash L2
        }
    }
}

// --------------------------------------------------------------------------
extern "C" void kernel_launch(void* const* d_in, const int* in_sizes, int n_in,
                              void* d_out, int out_size) {
    const float* feat   = (const float*)d_in[0];   // [60000, 2]
    const float* weight = (const float*)d_in[1];   // [27, 2, 64]
    const float* gamma  = (const float*)d_in[2];   // [64]
    const float* beta   = (const float*)d_in[3];   // [64]
    const int*   scat   = (const int*)d_in[4];     // [27, 60000]
    float* out = (float*)d_out;                    // [960000, 64]

    init_grid_kernel<<<(CELLS / 4 + 255) / 256, 256>>>();
    fill_grid_kernel<<<(NPTS + 255) / 256, 256>>>(scat);
    wbar_kernel<<<1, 32>>>(weight);
    fused_kernel<<<ROWS_TOTAL, 256>>>(
        (const float2*)feat, (const float2*)weight, gamma, beta, out);
}